// round 9
// baseline (speedup 1.0000x reference)
#include <cuda_runtime.h>
#include <cuda_bf16.h>
#include <cstdint>

#define NN 50000
#define NE 600000
#define FD 128
#define OUTC 64
#define MTILE 128
#define NTILES ((NN + MTILE - 1) / MTILE)   // 391
#define NNPAD (NTILES * MTILE)              // 50048
#define CHUNKE 16                            // edges per warp in segmented scatter

// ---------------- scratch (static device globals, zero-initialized) --------
__device__ float g_deg[NN];
__device__ float g_dis[NN];
__device__ int   g_cnt[NN];
__device__ int   g_fill[NN];
__device__ int4  g_edge[NE];                  // {row, bitcast(coef), col, 0} sorted by col
__device__ float g_buf[(size_t)NNPAD * FD];   // aggregation output (padded rows stay 0)
__device__ float g_h[(size_t)NN * FD];        // hidden activations
__device__ __nv_bfloat16 g_wimg_hi[2][16384]; // weight bf16 images, [n*128+k]
__device__ __nv_bfloat16 g_wimg_lo[2][16384];

// ---------------- mma / ldmatrix helpers (base sm_100 features) -------------
__device__ __forceinline__ uint32_t smem_u32(const void* p) {
    uint32_t a;
    asm("{ .reg .u64 t; cvta.to.shared.u64 t, %1; cvt.u32.u64 %0, t; }" : "=r"(a) : "l"(p));
    return a;
}
__device__ __forceinline__ void ldsm_x4(uint32_t* r, uint32_t addr) {
    asm volatile("ldmatrix.sync.aligned.m8n8.x4.shared.b16 {%0,%1,%2,%3}, [%4];"
        : "=r"(r[0]), "=r"(r[1]), "=r"(r[2]), "=r"(r[3]) : "r"(addr));
}
__device__ __forceinline__ void ldsm_x2(uint32_t* r, uint32_t addr) {
    asm volatile("ldmatrix.sync.aligned.m8n8.x2.shared.b16 {%0,%1}, [%2];"
        : "=r"(r[0]), "=r"(r[1]) : "r"(addr));
}
__device__ __forceinline__ void mma16816(float* c, const uint32_t* a, const uint32_t* b) {
    asm volatile("mma.sync.aligned.m16n8k16.row.col.f32.bf16.bf16.f32 "
        "{%0,%1,%2,%3}, {%4,%5,%6,%7}, {%8,%9}, {%0,%1,%2,%3};"
        : "+f"(c[0]), "+f"(c[1]), "+f"(c[2]), "+f"(c[3])
        : "r"(a[0]), "r"(a[1]), "r"(a[2]), "r"(a[3]), "r"(b[0]), "r"(b[1]));
}

// ---------------------------------------------------------------------------
// CSR build: init -> hist -> scan -> fill (ALL NE edges kept; self-loops coef=0)
// ---------------------------------------------------------------------------
__global__ void k_init() {
    int i = blockIdx.x * blockDim.x + threadIdx.x;
    if (i < NN) { g_deg[i] = 1.0f; g_cnt[i] = 0; }
}

__global__ void k_hist(const int* __restrict__ row, const int* __restrict__ col,
                       const float* __restrict__ ew) {
    int e = blockIdx.x * blockDim.x + threadIdx.x;
    if (e >= NE) return;
    int r = row[e], c = col[e];
    atomicAdd(&g_cnt[c], 1);                       // every edge gets a slot
    if (r != c) atomicAdd(&g_deg[c], ew[e]);       // degree excludes self-loops
}

#define SCAN_T 1024
#define SCHUNK 49   // 1024*49 = 50176 >= NN

__global__ void k_scan() {
    __shared__ int ssum[SCAN_T];
    int t = threadIdx.x;
    int beg = t * SCHUNK;
    int end = beg + SCHUNK; if (end > NN) end = NN;
    int s = 0;
    for (int i = beg; i < end; i++) s += g_cnt[i];
    ssum[t] = s;
    __syncthreads();
    for (int off = 1; off < SCAN_T; off <<= 1) {
        int v = (t >= off) ? ssum[t - off] : 0;
        __syncthreads();
        ssum[t] += v;
        __syncthreads();
    }
    int base = (t == 0) ? 0 : ssum[t - 1];
    for (int i = beg; i < end; i++) {
        g_fill[i] = base;
        base += g_cnt[i];
        g_dis[i] = rsqrtf(g_deg[i]);
    }
}

__global__ void k_fill(const int* __restrict__ row, const int* __restrict__ col,
                       const float* __restrict__ ew) {
    int e = blockIdx.x * blockDim.x + threadIdx.x;
    if (e >= NE) return;
    int r = row[e], c = col[e];
    float coef = (r == c) ? 0.0f : g_dis[r] * ew[e] * g_dis[c];
    int pos = atomicAdd(&g_fill[c], 1);
    g_edge[pos] = make_int4(r, __float_as_int(coef), c, 0);
}

// ---------------------------------------------------------------------------
// weight prep: fp32 W -> bf16 hi/lo images, plain [n][k] layout
// ---------------------------------------------------------------------------
__global__ void k_wprep(const float* __restrict__ W1, const float* __restrict__ Wmu,
                        const float* __restrict__ Wls) {
    int idx = blockIdx.x * blockDim.x + threadIdx.x;
    if (idx >= 2 * 16384) return;
    int layer = idx >> 14, e = idx & 16383;
    int n = e >> 7, k = e & 127;
    float w;
    if (layer == 0) w = W1[e];
    else            w = (n < 64) ? Wmu[n * 128 + k] : Wls[(n - 64) * 128 + k];
    __nv_bfloat16 hi = __float2bfloat16(w);
    __nv_bfloat16 lo = __float2bfloat16(w - __bfloat162float(hi));
    g_wimg_hi[layer][e] = hi;
    g_wimg_lo[layer][e] = lo;
}

// ---------------------------------------------------------------------------
// self-loop init: buf[i,:] = src[i,:] / deg[i]
// ---------------------------------------------------------------------------
template <bool FROM_H>
__global__ void k_selfinit(const float4* __restrict__ src_in) {
    int idx = blockIdx.x * blockDim.x + threadIdx.x;
    if (idx >= NN * 32) return;
    const float4* src = FROM_H ? (const float4*)g_h : src_in;
    int i = idx >> 5;
    float d = g_dis[i];
    float d2 = d * d;
    float4 v = src[idx];
    v.x *= d2; v.y *= d2; v.z *= d2; v.w *= d2;
    ((float4*)g_buf)[idx] = v;
}

// ---------------------------------------------------------------------------
// segmented scatter over col-sorted edges: warp handles CHUNKE consecutive
// edges, register-accumulates runs with equal col, flushes red.v4 on change.
// nedge is compile-time NE (self-loops carry coef 0, contribute nothing).
// ---------------------------------------------------------------------------
__device__ __forceinline__ void flush_v4(int node, int lane, float4 a) {
    float* dst = g_buf + (size_t)node * FD + lane * 4;
    asm volatile("red.global.add.v4.f32 [%0], {%1,%2,%3,%4};"
                 :: "l"(dst), "f"(a.x), "f"(a.y), "f"(a.z), "f"(a.w)
                 : "memory");
}

template <bool FROM_H>
__global__ void __launch_bounds__(256) k_segscatter(const float4* __restrict__ src_in) {
    int warp = (blockIdx.x * blockDim.x + threadIdx.x) >> 5;
    int lane = threadIdx.x & 31;
    int s = warp * CHUNKE;
    if (s >= NE) return;
    int end = s + CHUNKE; if (end > NE) end = NE;
    const float4* src = FROM_H ? (const float4*)g_h : src_in;

    float4 acc = make_float4(0.f, 0.f, 0.f, 0.f);
    int cur = -1;

    for (int e0 = s; e0 < end; e0 += 4) {
        int m = end - e0; if (m > 4) m = 4;
        int4 ed[4];
        float4 v[4];
        #pragma unroll
        for (int i = 0; i < 4; i++)
            if (i < m) ed[i] = g_edge[e0 + i];
        #pragma unroll
        for (int i = 0; i < 4; i++)
            if (i < m) v[i] = __ldg(&src[(size_t)ed[i].x * 32 + lane]);
        #pragma unroll
        for (int i = 0; i < 4; i++) {
            if (i < m) {
                if (ed[i].z != cur) {
                    if (cur >= 0) flush_v4(cur, lane, acc);
                    acc = make_float4(0.f, 0.f, 0.f, 0.f);
                    cur = ed[i].z;
                }
                float cf = __int_as_float(ed[i].y);
                acc.x = fmaf(v[i].x, cf, acc.x);
                acc.y = fmaf(v[i].y, cf, acc.y);
                acc.z = fmaf(v[i].z, cf, acc.z);
                acc.w = fmaf(v[i].w, cf, acc.w);
            }
        }
    }
    if (cur >= 0) flush_v4(cur, lane, acc);
}

// ---------------------------------------------------------------------------
// HMMA GEMM (R6 proven): out[128-tile,128] = buf_tile @ W^T (+bias, opt relu)
// ---------------------------------------------------------------------------
#define APITCH 136
#define TILE_B (128 * APITCH * 2)   // 34816
#define SM_AHI 1024
#define SM_ALO (SM_AHI + TILE_B)
#define SM_BHI (SM_ALO + TILE_B)
#define SM_BLO (SM_BHI + TILE_B)
#define SM_TOTAL (SM_BLO + TILE_B)
#define EPI_PITCH 129

template <int MODE>
__global__ void __launch_bounds__(256) k_mmagemm(const float* __restrict__ ba,
                                                 const float* __restrict__ bb,
                                                 float* __restrict__ outA,
                                                 float* __restrict__ outB) {
    extern __shared__ char smem[];
    uint32_t sb = smem_u32(smem);
    int tid = threadIdx.x;
    int wid = tid >> 5;
    int lane = tid & 31;
    int row0 = blockIdx.x * MTILE;

    float* sbias = (float*)smem;
    if (tid < 128) {
        if (MODE == 0) sbias[tid] = ba[tid];
        else           sbias[tid] = (tid < 64) ? ba[tid] : bb[tid - 64];
    }

    for (int i = tid; i < 128 * 16; i += 256) {
        int n = i >> 4, seg = i & 15;
        uint32_t doff = (uint32_t)n * (APITCH * 2) + seg * 16;
        *(uint4*)(smem + SM_BHI + doff) = ((const uint4*)g_wimg_hi[MODE])[i];
        *(uint4*)(smem + SM_BLO + doff) = ((const uint4*)g_wimg_lo[MODE])[i];
    }

    for (int it = tid; it < 128 * 32; it += 256) {
        int row = it >> 5, seg = it & 31;
        float4 v = ((const float4*)(g_buf + (size_t)(row0 + row) * FD))[seg];
        __nv_bfloat16 h0 = __float2bfloat16(v.x), h1 = __float2bfloat16(v.y);
        __nv_bfloat16 h2 = __float2bfloat16(v.z), h3 = __float2bfloat16(v.w);
        __nv_bfloat16 l0 = __float2bfloat16(v.x - __bfloat162float(h0));
        __nv_bfloat16 l1 = __float2bfloat16(v.y - __bfloat162float(h1));
        __nv_bfloat16 l2 = __float2bfloat16(v.z - __bfloat162float(h2));
        __nv_bfloat16 l3 = __float2bfloat16(v.w - __bfloat162float(h3));
        uint32_t doff = (uint32_t)row * (APITCH * 2) + seg * 8;
        __nv_bfloat162 hv0(h0, h1), hv1(h2, h3), lv0(l0, l1), lv1(l2, l3);
        *(__nv_bfloat162*)(smem + SM_AHI + doff) = hv0;
        *(__nv_bfloat162*)(smem + SM_AHI + doff + 4) = hv1;
        *(__nv_bfloat162*)(smem + SM_ALO + doff) = lv0;
        *(__nv_bfloat162*)(smem + SM_ALO + doff + 4) = lv1;
    }
    __syncthreads();

    float acc[16][4];
    #pragma unroll
    for (int nt = 0; nt < 16; nt++)
        #pragma unroll
        for (int i = 0; i < 4; i++) acc[nt][i] = 0.0f;

    int ar = lane & 15, acg = lane >> 4;
    uint32_t a_base = (uint32_t)(16 * wid + ar) * (APITCH * 2) + acg * 16;
    int bn = lane & 7, bkg = (lane >> 3) & 1;

    #pragma unroll
    for (int kc = 0; kc < 8; kc++) {
        uint32_t a_hi[4], a_lo[4];
        uint32_t aoff = a_base + kc * 32;
        ldsm_x4(a_hi, sb + SM_AHI + aoff);
        ldsm_x4(a_lo, sb + SM_ALO + aoff);
        #pragma unroll
        for (int nt = 0; nt < 16; nt++) {
            uint32_t boff = (uint32_t)(nt * 8 + bn) * (APITCH * 2) + kc * 32 + bkg * 16;
            uint32_t b_hi[2], b_lo[2];
            ldsm_x2(b_hi, sb + SM_BHI + boff);
            ldsm_x2(b_lo, sb + SM_BLO + boff);
            mma16816(acc[nt], a_hi, b_hi);
            mma16816(acc[nt], a_hi, b_lo);
            mma16816(acc[nt], a_lo, b_hi);
        }
    }
    __syncthreads();

    float* epi = (float*)(smem + SM_AHI);
    int g = lane >> 2, cp = (lane & 3) * 2;
    #pragma unroll
    for (int nt = 0; nt < 16; nt++) {
        int colb = nt * 8 + cp;
        epi[(16 * wid + g) * EPI_PITCH + colb]     = acc[nt][0];
        epi[(16 * wid + g) * EPI_PITCH + colb + 1] = acc[nt][1];
        epi[(16 * wid + g + 8) * EPI_PITCH + colb]     = acc[nt][2];
        epi[(16 * wid + g + 8) * EPI_PITCH + colb + 1] = acc[nt][3];
    }
    __syncthreads();

    for (int it = tid; it < 128 * 128; it += 256) {
        int row = it >> 7, col = it & 127;
        int grow = row0 + row;
        if (grow >= NN) continue;
        float v = epi[row * EPI_PITCH + col] + sbias[col];
        if (MODE == 0) {
            g_h[(size_t)grow * FD + col] = fmaxf(v, 0.0f);
        } else {
            if (col < 64) outA[(size_t)grow * OUTC + col] = v;
            else          outB[(size_t)grow * OUTC + col - 64] = v;
        }
    }
}

// ---------------------------------------------------------------------------
extern "C" void kernel_launch(void* const* d_in, const int* in_sizes, int n_in,
                              void* d_out, int out_size) {
    const float* x   = (const float*)d_in[0];
    const int*   ei  = (const int*)d_in[1];
    const float* ew  = (const float*)d_in[2];
    const float* W1  = (const float*)d_in[3];
    const float* b1  = (const float*)d_in[4];
    const float* Wmu = (const float*)d_in[5];
    const float* bmu = (const float*)d_in[6];
    const float* Wls = (const float*)d_in[7];
    const float* bls = (const float*)d_in[8];
    const int* row = ei;
    const int* col = ei + NE;

    float* mu = (float*)d_out;
    float* ls = mu + (size_t)NN * OUTC;

    static bool s_attr = false;
    if (!s_attr) {
        cudaFuncSetAttribute(k_mmagemm<0>, cudaFuncAttributeMaxDynamicSharedMemorySize, SM_TOTAL);
        cudaFuncSetAttribute(k_mmagemm<1>, cudaFuncAttributeMaxDynamicSharedMemorySize, SM_TOTAL);
        s_attr = true;
    }

    int tb = 256;
    int gN  = (NN + tb - 1) / tb;
    int gE  = (NE + tb - 1) / tb;
    int gF4 = (NN * 32 + tb - 1) / tb;
    int nWarps = (NE + CHUNKE - 1) / CHUNKE;
    int gSeg = (nWarps * 32 + tb - 1) / tb;

    // CSR build (amortized over both layers)
    k_init<<<gN, tb>>>();
    k_hist<<<gE, tb>>>(row, col, ew);
    k_scan<<<1, SCAN_T>>>();
    k_fill<<<gE, tb>>>(row, col, ew);
    k_wprep<<<(2 * 16384 + tb - 1) / tb, tb>>>(W1, Wmu, Wls);

    // layer 1
    k_selfinit<false><<<gF4, tb>>>((const float4*)x);
    k_segscatter<false><<<gSeg, tb>>>((const float4*)x);
    k_mmagemm<0><<<NTILES, tb, SM_TOTAL>>>(b1, nullptr, nullptr, nullptr);

    // layer 2
    k_selfinit<true><<<gF4, tb>>>(nullptr);
    k_segscatter<true><<<gSeg, tb>>>(nullptr);
    k_mmagemm<1><<<NTILES, tb, SM_TOTAL>>>(bmu, bls, mu, ls);
}